// round 5
// baseline (speedup 1.0000x reference)
#include <cuda_runtime.h>
#include <math.h>

#define NMAT 256
#define D    64
#define DD   4096
#define ST   68   // shared-memory row stride (float4-aligned, bank-spreading)

// ---------------- device scratch (no allocations allowed) ----------------
__device__ float g_L[NMAT * DD];   // log(X_i), row-major per matrix
__device__ float g_W[NMAT * NMAT]; // kernel weights
__device__ float g_B[NMAT * DD];   // log(X_k) + M_k
__device__ float g_rs[NMAT];       // row sums of W
__device__ float g_cs[NMAT];       // col sums of W

// ---------------- 64x64 shared-memory GEMM, 4x4 tile per thread ----------
// acc += A * B  (A,B: 64x64 with row stride ST in shared memory)
__device__ __forceinline__ void mm64(const float* __restrict__ A,
                                     const float* __restrict__ B,
                                     float acc[4][4], int i0, int j0)
{
#define FMA4ROW(r, aR)                                                        \
    acc[r][0] += aR.x * b0.x + aR.y * b1.x + aR.z * b2.x + aR.w * b3.x;       \
    acc[r][1] += aR.x * b0.y + aR.y * b1.y + aR.z * b2.y + aR.w * b3.y;       \
    acc[r][2] += aR.x * b0.z + aR.y * b1.z + aR.z * b2.z + aR.w * b3.z;       \
    acc[r][3] += aR.x * b0.w + aR.y * b1.w + aR.z * b2.w + aR.w * b3.w;

#pragma unroll 4
    for (int k = 0; k < D; k += 4) {
        float4 a0 = *reinterpret_cast<const float4*>(A + (i0 + 0) * ST + k);
        float4 a1 = *reinterpret_cast<const float4*>(A + (i0 + 1) * ST + k);
        float4 a2 = *reinterpret_cast<const float4*>(A + (i0 + 2) * ST + k);
        float4 a3 = *reinterpret_cast<const float4*>(A + (i0 + 3) * ST + k);
        float4 b0 = *reinterpret_cast<const float4*>(B + (k + 0) * ST + j0);
        float4 b1 = *reinterpret_cast<const float4*>(B + (k + 1) * ST + j0);
        float4 b2 = *reinterpret_cast<const float4*>(B + (k + 2) * ST + j0);
        float4 b3 = *reinterpret_cast<const float4*>(B + (k + 3) * ST + j0);
        FMA4ROW(0, a0)
        FMA4ROW(1, a1)
        FMA4ROW(2, a2)
        FMA4ROW(3, a3)
    }
#undef FMA4ROW
}

// =====================================================================
// K1: matrix log via inverse scaling-and-squaring + Newton-Schulz sqrt
// one block (256 threads) per matrix
// =====================================================================
__global__ void k_logm(const float* __restrict__ X)
{
    extern __shared__ float sh[];
    float* Y = sh;              // current iterate / E
    float* Z = sh + D * ST;     // NS dual iterate / Horner accumulator
    float* P = sh + 2 * D * ST; // product buffer

    __shared__ float red[D];
    __shared__ float vv[D], wv[D];
    __shared__ float bc[2];

    const int tid = threadIdx.x;
    const int m   = blockIdx.x;
    const int i0  = (tid >> 4) * 4;
    const int j0  = (tid & 15) * 4;
    const float* Xg = X + (size_t)m * DD;

    for (int idx = tid; idx < DD; idx += 256)
        Y[(idx >> 6) * ST + (idx & 63)] = Xg[idx];
    if (tid < D) vv[tid] = 1.0f;
    __syncthreads();

    // --- power iteration: upper bound on lambda_max ---
    for (int it = 0; it < 12; it++) {
        if (tid < D) {
            float s = 0.0f;
#pragma unroll 8
            for (int k = 0; k < D; k++) s += Y[tid * ST + k] * vv[k];
            wv[tid]  = s;
            red[tid] = s * s;
        }
        __syncthreads();
        if (tid == 0) {
            float n2 = 0.0f;
            for (int k = 0; k < D; k++) n2 += red[k];
            bc[0] = sqrtf(n2);
            bc[1] = rsqrtf(n2);
        }
        __syncthreads();
        if (tid < D) vv[tid] = wv[tid] * bc[1];
        __syncthreads();
    }
    float bmax = fmaxf(bc[0] * 1.10f, 0.75f); // safe upper estimate of lambda_max

    // exact lower bounds: lambda_min(X) >= 0.5 by construction
    const float alo[4]  = {0.5f, 0.70710678f, 0.84089642f, 0.91700404f};
    const int   nsit[4] = {9, 6, 5, 4};

    // --- 4 levels of Newton-Schulz square roots with midpoint scaling ---
    for (int lev = 0; lev < 4; lev++) {
        float c  = 0.5f * (alo[lev] + bmax);
        float ic = 1.0f / c;
        for (int idx = tid; idx < DD; idx += 256) {
            int r = idx >> 6, cc = idx & 63;
            Y[r * ST + cc] *= ic;
            Z[r * ST + cc] = (r == cc) ? 1.0f : 0.0f;
        }
        __syncthreads();
        for (int it = 0; it < nsit[lev]; it++) {
            float accP[4][4] = {};
            mm64(Z, Y, accP, i0, j0);     // P = Z*Y
            // P is a distinct buffer: safe to write while others still read Y,Z
#pragma unroll
            for (int r = 0; r < 4; r++)
#pragma unroll
                for (int c2 = 0; c2 < 4; c2++)
                    P[(i0 + r) * ST + j0 + c2] = accP[r][c2];
            __syncthreads();
            float accY[4][4] = {}, accZ[4][4] = {};
            mm64(Y, P, accY, i0, j0);     // Y*P
            mm64(P, Z, accZ, i0, j0);     // P*Z
            __syncthreads();
#pragma unroll
            for (int r = 0; r < 4; r++)
#pragma unroll
                for (int c2 = 0; c2 < 4; c2++) {
                    int o = (i0 + r) * ST + j0 + c2;
                    Y[o] = 1.5f * Y[o] - 0.5f * accY[r][c2];
                    Z[o] = 1.5f * Z[o] - 0.5f * accZ[r][c2];
                }
            __syncthreads();
        }
        float sc = sqrtf(c);
        for (int idx = tid; idx < DD; idx += 256)
            Y[(idx >> 6) * ST + (idx & 63)] *= sc;
        __syncthreads();
        bmax = sqrtf(bmax);
    }

    // --- log(Y) via degree-9 Taylor in E = Y - I (Horner) ---
    if (tid < D) Y[tid * ST + tid] -= 1.0f;   // Y := E
    for (int idx = tid; idx < DD; idx += 256) {
        int r = idx >> 6, cc = idx & 63;
        Z[r * ST + cc] = (r == cc) ? (1.0f / 9.0f) : 0.0f; // S = a9*I
    }
    __syncthreads();
    for (int n = 8; n >= 1; n--) {
        float acc[4][4] = {};
        mm64(Z, Y, acc, i0, j0);          // S*E
        __syncthreads();
        float an = ((n & 1) ? 1.0f : -1.0f) / (float)n;
#pragma unroll
        for (int r = 0; r < 4; r++)
#pragma unroll
            for (int c2 = 0; c2 < 4; c2++)
                Z[(i0 + r) * ST + j0 + c2] =
                    acc[r][c2] + ((i0 + r == j0 + c2) ? an : 0.0f);
        __syncthreads();
    }
    float acc[4][4] = {};
    mm64(Z, Y, acc, i0, j0);              // log(Y4) = S1*E
    float* Lg = g_L + (size_t)m * DD;
#pragma unroll
    for (int r = 0; r < 4; r++)
#pragma unroll
        for (int c2 = 0; c2 < 4; c2++)
            Lg[(i0 + r) * D + j0 + c2] = 16.0f * acc[r][c2]; // log X = 2^4 log(Y4)
}

// =====================================================================
// K2: pairwise squared distances + kernel weights  (direct, no cancellation)
// pds[i][j] = sum_ab (L_j - L_i + eps)^2 ;  W = exp(-0.5*pds/bw^2)
// 32x32 pair tile per block, grid (8,8)
// =====================================================================
__global__ void k_pds(const float* __restrict__ bwp)
{
    __shared__ float Li[32 * 65], Lj[32 * 65];
    const int tid = threadIdx.x;
    const int tx  = tid & 15, ty = tid >> 4;
    const int ib  = blockIdx.y * 32, jb = blockIdx.x * 32;
    const float eps = 1e-7f;
    float a00 = 0, a01 = 0, a10 = 0, a11 = 0;

    for (int kc = 0; kc < DD; kc += 64) {
        for (int idx = tid; idx < 2048; idx += 256) {
            int r = idx >> 6, kk = idx & 63;
            Li[r * 65 + kk] = g_L[(size_t)(ib + r) * DD + kc + kk];
            Lj[r * 65 + kk] = g_L[(size_t)(jb + r) * DD + kc + kk];
        }
        __syncthreads();
#pragma unroll 8
        for (int k = 0; k < 64; k++) {
            float li0 = Li[ty * 65 + k], li1 = Li[(ty + 16) * 65 + k];
            float lj0 = Lj[tx * 65 + k], lj1 = Lj[(tx + 16) * 65 + k];
            float d;
            d = lj0 - li0 + eps; a00 += d * d;
            d = lj1 - li0 + eps; a01 += d * d;
            d = lj0 - li1 + eps; a10 += d * d;
            d = lj1 - li1 + eps; a11 += d * d;
        }
        __syncthreads();
    }
    float bw = bwp[0];
    float g  = -0.5f / (bw * bw);
    g_W[(size_t)(ib + ty)      * NMAT + jb + tx]      = expf(g * a00);
    g_W[(size_t)(ib + ty)      * NMAT + jb + tx + 16] = expf(g * a01);
    g_W[(size_t)(ib + ty + 16) * NMAT + jb + tx]      = expf(g * a10);
    g_W[(size_t)(ib + ty + 16) * NMAT + jb + tx + 16] = expf(g * a11);
}

// =====================================================================
// K3: row sums and column sums of W (one block per index k)
// =====================================================================
__global__ void k_sums()
{
    __shared__ float red[256];
    const int k = blockIdx.x, tid = threadIdx.x;

    red[tid] = g_W[(size_t)k * NMAT + tid];
    __syncthreads();
    for (int off = 128; off; off >>= 1) {
        if (tid < off) red[tid] += red[tid + off];
        __syncthreads();
    }
    if (tid == 0) g_rs[k] = red[0];
    __syncthreads();

    red[tid] = g_W[(size_t)tid * NMAT + k];
    __syncthreads();
    for (int off = 128; off; off >>= 1) {
        if (tid < off) red[tid] += red[tid + off];
        __syncthreads();
    }
    if (tid == 0) g_cs[k] = red[0];
}

// =====================================================================
// K4: B_k = logX_k*(1 - cs_k/rs_k) + (W^T L)_k / rs_k
// GEMM C[256 x 4096] = W^T[256x256] * L[256x4096], 64x64 tiles
// =====================================================================
__global__ void k_num()
{
    __shared__ float At[64 * ST]; // At[k][j] = W[j][k]
    __shared__ float Bt[64 * ST]; // Bt[j][c] = L[j][c]
    const int tid = threadIdx.x;
    const int i0  = (tid >> 4) * 4, j0 = (tid & 15) * 4;
    const int k0  = blockIdx.y * 64; // output row (matrix index k) block
    const int c0  = blockIdx.x * 64; // output column block
    float acc[4][4] = {};

    for (int jc = 0; jc < NMAT; jc += 64) {
        for (int idx = tid; idx < 4096; idx += 256) {
            int jj = idx >> 6, kk = idx & 63;
            At[kk * ST + jj] = g_W[(size_t)(jc + jj) * NMAT + k0 + kk];
            Bt[jj * ST + kk] = g_L[(size_t)(jc + jj) * DD + c0 + kk];
        }
        __syncthreads();
        mm64(At, Bt, acc, i0, j0);
        __syncthreads();
    }
#pragma unroll
    for (int r = 0; r < 4; r++) {
        int k = k0 + i0 + r;
        float irs  = 1.0f / g_rs[k];
        float coef = 1.0f - g_cs[k] * irs;
#pragma unroll
        for (int c2 = 0; c2 < 4; c2++) {
            int col = c0 + j0 + c2;
            g_B[(size_t)k * DD + col] =
                acc[r][c2] * irs + coef * g_L[(size_t)k * DD + col];
        }
    }
}

// =====================================================================
// K5: matrix exp via scaling-and-squaring (degree-7 Taylor), block per matrix
// =====================================================================
__global__ void k_expm(float* __restrict__ out)
{
    extern __shared__ float sh[];
    float* A = sh;
    float* S = sh + D * ST;
    float* P = sh + 2 * D * ST;
    __shared__ float red[256];

    const int tid = threadIdx.x;
    const int m   = blockIdx.x;
    const int i0  = (tid >> 4) * 4, j0 = (tid & 15) * 4;
    const float* Bg = g_B + (size_t)m * DD;

    float p = 0.0f;
    for (int idx = tid; idx < DD; idx += 256) {
        float v = Bg[idx];
        A[(idx >> 6) * ST + (idx & 63)] = v;
        p += v * v;
    }
    red[tid] = p;
    __syncthreads();
    for (int off = 128; off; off >>= 1) {
        if (tid < off) red[tid] += red[tid + off];
        __syncthreads();
    }
    float nf = sqrtf(red[0]);
    int s = 0;
    while (nf > 0.25f && s < 30) { nf *= 0.5f; s++; }
    float sc = ldexpf(1.0f, -s);
    for (int idx = tid; idx < DD; idx += 256)
        A[(idx >> 6) * ST + (idx & 63)] *= sc;
    __syncthreads();

    // S = I + A/7
    for (int idx = tid; idx < DD; idx += 256) {
        int r = idx >> 6, cc = idx & 63;
        S[r * ST + cc] = A[r * ST + cc] * (1.0f / 7.0f) + ((r == cc) ? 1.0f : 0.0f);
    }
    __syncthreads();
    for (int n = 6; n >= 1; n--) {
        float acc[4][4] = {};
        mm64(A, S, acc, i0, j0);
        __syncthreads();
        float in = 1.0f / (float)n;
#pragma unroll
        for (int r = 0; r < 4; r++)
#pragma unroll
            for (int c2 = 0; c2 < 4; c2++)
                S[(i0 + r) * ST + j0 + c2] =
                    acc[r][c2] * in + ((i0 + r == j0 + c2) ? 1.0f : 0.0f);
        __syncthreads();
    }

    // square s times (ping-pong S <-> P)
    float* cur = S;
    float* oth = P;
    for (int q = 0; q < s; q++) {
        float acc[4][4] = {};
        mm64(cur, cur, acc, i0, j0);
#pragma unroll
        for (int r = 0; r < 4; r++)
#pragma unroll
            for (int c2 = 0; c2 < 4; c2++)
                oth[(i0 + r) * ST + j0 + c2] = acc[r][c2];
        __syncthreads();
        float* t = cur; cur = oth; oth = t;
    }

    float* Og = out + (size_t)m * DD;
#pragma unroll
    for (int r = 0; r < 4; r++)
#pragma unroll
        for (int c2 = 0; c2 < 4; c2++)
            Og[(i0 + r) * D + j0 + c2] = cur[(i0 + r) * ST + j0 + c2];
}

// =====================================================================
extern "C" void kernel_launch(void* const* d_in, const int* in_sizes, int n_in,
                              void* d_out, int out_size)
{
    const float* X  = (const float*)d_in[0];
    const float* bw = (const float*)d_in[1];
    float* out      = (float*)d_out;

    const int shmem = 3 * D * ST * sizeof(float); // 52224 B > 48KB default
    cudaFuncSetAttribute(k_logm, cudaFuncAttributeMaxDynamicSharedMemorySize, shmem);
    cudaFuncSetAttribute(k_expm, cudaFuncAttributeMaxDynamicSharedMemorySize, shmem);

    k_logm<<<NMAT, 256, shmem>>>(X);
    k_pds<<<dim3(8, 8), 256>>>(bw);
    k_sums<<<NMAT, 256>>>();
    k_num<<<dim3(DD / 64, NMAT / 64), 256>>>();
    k_expm<<<NMAT, 256, shmem>>>(out);
}

// round 7
// speedup vs baseline: 1.2273x; 1.2273x over previous
#include <cuda_runtime.h>
#include <math.h>

#define NMAT 256
#define D    64
#define DD   4096
#define ST   68   // shared-memory row stride (float4-aligned, bank-spreading)

// ---------------- device scratch (no allocations allowed) ----------------
__device__ float g_L[NMAT * DD];   // log(X_i), row-major per matrix
__device__ float g_W[NMAT * NMAT]; // kernel weights
__device__ float g_B[NMAT * DD];   // log(X_k) + M_k
__device__ float g_rs[NMAT];       // row sums of W
__device__ float g_cs[NMAT];       // col sums of W

// ---------------- 64x64 shared-memory GEMM, 4x4 tile per thread ----------
// acc += A * B  (A,B: 64x64 with row stride ST in shared memory)
__device__ __forceinline__ void mm64(const float* __restrict__ A,
                                     const float* __restrict__ B,
                                     float acc[4][4], int i0, int j0)
{
#define FMA4ROW(r, aR)                                                        \
    acc[r][0] += aR.x * b0.x + aR.y * b1.x + aR.z * b2.x + aR.w * b3.x;       \
    acc[r][1] += aR.x * b0.y + aR.y * b1.y + aR.z * b2.y + aR.w * b3.y;       \
    acc[r][2] += aR.x * b0.z + aR.y * b1.z + aR.z * b2.z + aR.w * b3.z;       \
    acc[r][3] += aR.x * b0.w + aR.y * b1.w + aR.z * b2.w + aR.w * b3.w;

#pragma unroll 4
    for (int k = 0; k < D; k += 4) {
        float4 a0 = *reinterpret_cast<const float4*>(A + (i0 + 0) * ST + k);
        float4 a1 = *reinterpret_cast<const float4*>(A + (i0 + 1) * ST + k);
        float4 a2 = *reinterpret_cast<const float4*>(A + (i0 + 2) * ST + k);
        float4 a3 = *reinterpret_cast<const float4*>(A + (i0 + 3) * ST + k);
        float4 b0 = *reinterpret_cast<const float4*>(B + (k + 0) * ST + j0);
        float4 b1 = *reinterpret_cast<const float4*>(B + (k + 1) * ST + j0);
        float4 b2 = *reinterpret_cast<const float4*>(B + (k + 2) * ST + j0);
        float4 b3 = *reinterpret_cast<const float4*>(B + (k + 3) * ST + j0);
        FMA4ROW(0, a0)
        FMA4ROW(1, a1)
        FMA4ROW(2, a2)
        FMA4ROW(3, a3)
    }
#undef FMA4ROW
}

// store a 4x4 tile + its mirror (symmetric output)
__device__ __forceinline__ void store_sym(float* __restrict__ C,
                                          const float acc[4][4],
                                          int i0, int j0, bool diag)
{
#pragma unroll
    for (int r = 0; r < 4; r++)
#pragma unroll
        for (int c = 0; c < 4; c++)
            C[(i0 + r) * ST + j0 + c] = acc[r][c];
    if (!diag) {
#pragma unroll
        for (int r = 0; r < 4; r++)
#pragma unroll
            for (int c = 0; c < 4; c++)
                C[(j0 + c) * ST + i0 + r] = acc[r][c];
    }
}

// map tid -> upper-triangle 4x4 tile (136 tiles over a 16x16 tile grid)
__device__ __forceinline__ void tri_map(int tid, int& i0, int& j0,
                                        bool& act, bool& diag)
{
    act = (tid < 136);
    int ti = 0, rem = tid;
    if (act) {
        while (rem >= 16 - ti) { rem -= 16 - ti; ti++; }
        i0 = ti * 4;
        j0 = (ti + rem) * 4;
        diag = (i0 == j0);
    } else {
        i0 = 0; j0 = 0; diag = true;
    }
}

// =====================================================================
// K1: matrix log. 3 levels of Newton-Schulz inverse-scaled sqrt,
// geometric-mean centering, degree-9 log-Taylor via Paterson-Stockmeyer.
// All GEMM outputs symmetric -> upper-triangle tiles only + mirror.
// =====================================================================
__global__ void k_logm(const float* __restrict__ X)
{
    extern __shared__ float sh[];
    float* Y = sh;              // iterate / E
    float* Z = sh + D * ST;     // NS dual / E^2
    float* P = sh + 2 * D * ST; // product / E^3
    float* W = sh + 3 * D * ST; // PS scratch

    __shared__ float red[D];
    __shared__ float vv[D], wv[D];
    __shared__ float bc[2];

    const int tid = threadIdx.x;
    const int m   = blockIdx.x;
    int i0, j0; bool act, diag;
    tri_map(tid, i0, j0, act, diag);
    const float* Xg = X + (size_t)m * DD;

    for (int idx = tid; idx < DD; idx += 256)
        Y[(idx >> 6) * ST + (idx & 63)] = Xg[idx];
    if (tid < D) vv[tid] = 1.0f;
    __syncthreads();

    // --- power iteration: upper bound on lambda_max ---
    for (int it = 0; it < 12; it++) {
        if (tid < D) {
            float s = 0.0f;
#pragma unroll 8
            for (int k = 0; k < D; k++) s += Y[tid * ST + k] * vv[k];
            wv[tid]  = s;
            red[tid] = s * s;
        }
        __syncthreads();
        if (tid == 0) {
            float n2 = 0.0f;
            for (int k = 0; k < D; k++) n2 += red[k];
            bc[0] = sqrtf(n2);
            bc[1] = rsqrtf(n2);
        }
        __syncthreads();
        if (tid < D) vv[tid] = wv[tid] * bc[1];
        __syncthreads();
    }
    float bmax = fmaxf(bc[0] * 1.10f, 0.75f);

    // lambda_min(X) >= 0.5 exactly by construction
    const float alo[3]  = {0.5f, 0.70710678f, 0.84089642f};
    const int   nsit[3] = {9, 6, 5};

    for (int lev = 0; lev < 3; lev++) {
        float c  = 0.5f * (alo[lev] + bmax);
        float ic = 1.0f / c;
        for (int idx = tid; idx < DD; idx += 256)
            Y[(idx >> 6) * ST + (idx & 63)] *= ic;
        __syncthreads();

        // --- first NS iteration: Z0 = I, so P = Y, Z1 = (3I - Y)/2,
        //     Y1 = 1.5Y - 0.5*Y*Y  (only 1 GEMM) ---
        {
            float accY[4][4] = {};
            if (act) mm64(Y, Y, accY, i0, j0);
            __syncthreads();
            if (act) {
#pragma unroll
                for (int r = 0; r < 4; r++)
#pragma unroll
                    for (int c2 = 0; c2 < 4; c2++) {
                        int o = (i0 + r) * ST + j0 + c2;
                        float yv   = Y[o];
                        float ynew = 1.5f * yv - 0.5f * accY[r][c2];
                        float znew = 1.5f * ((i0 + r == j0 + c2) ? 1.0f : 0.0f)
                                     - 0.5f * yv;
                        Y[o] = ynew; Z[o] = znew;
                        if (!diag) {
                            int om = (j0 + c2) * ST + i0 + r;
                            Y[om] = ynew; Z[om] = znew;
                        }
                    }
            }
            __syncthreads();
        }

        for (int it = 1; it < nsit[lev]; it++) {
            const bool lastNoZ = (lev == 2) && (it == nsit[2] - 1);
            float accP[4][4] = {};
            if (act) mm64(Z, Y, accP, i0, j0);   // P = Z*Y
            if (act) store_sym(P, accP, i0, j0, diag); // distinct buffer: safe
            __syncthreads();
            float accY[4][4] = {}, accZ[4][4] = {};
            if (act) {
                mm64(Y, P, accY, i0, j0);        // Y*P
                if (!lastNoZ) mm64(P, Z, accZ, i0, j0); // P*Z
            }
            __syncthreads();
            if (act) {
#pragma unroll
                for (int r = 0; r < 4; r++)
#pragma unroll
                    for (int c2 = 0; c2 < 4; c2++) {
                        int o  = (i0 + r) * ST + j0 + c2;
                        int om = (j0 + c2) * ST + i0 + r;
                        float ynew = 1.5f * Y[o] - 0.5f * accY[r][c2];
                        Y[o] = ynew;
                        if (!diag) Y[om] = ynew;
                        if (!lastNoZ) {
                            float znew = 1.5f * Z[o] - 0.5f * accZ[r][c2];
                            Z[o] = znew;
                            if (!diag) Z[om] = znew;
                        }
                    }
            }
            __syncthreads();
        }
        float sc = sqrtf(c);
        for (int idx = tid; idx < DD; idx += 256)
            Y[(idx >> 6) * ST + (idx & 63)] *= sc;
        __syncthreads();
        bmax = sqrtf(bmax);
    }

    // --- centering: gamma = sqrt(lo*hi), E = Y/gamma - I ---
    const float gm = sqrtf(0.91700404f * bmax); // lo = 0.5^(1/8)
    const float ig = 1.0f / gm;
    for (int idx = tid; idx < DD; idx += 256) {
        int r = idx >> 6, cc = idx & 63;
        Y[r * ST + cc] = Y[r * ST + cc] * ig - ((r == cc) ? 1.0f : 0.0f);
    }
    __syncthreads();

    // --- degree-9 log Taylor via Paterson-Stockmeyer, q = E^3 ---
    // p = C0 + q*(C1 + q*(C2 + a9*q)),  a_n = (-1)^(n+1)/n
    {
        float acc[4][4] = {};
        if (act) mm64(Y, Y, acc, i0, j0);          // E^2
        if (act) store_sym(Z, acc, i0, j0, diag);
        __syncthreads();
    }
    {
        float acc[4][4] = {};
        if (act) mm64(Y, Z, acc, i0, j0);          // E^3
        if (act) store_sym(P, acc, i0, j0, diag);
        __syncthreads();
    }
    // W = C2 + a9*E^3 = -1/6 I + 1/7 E - 1/8 E^2 + 1/9 E^3 (full pass)
    for (int idx = tid; idx < DD; idx += 256) {
        int r = idx >> 6, cc = idx & 63;
        int o = r * ST + cc;
        W[o] = (1.0f / 7.0f) * Y[o] - 0.125f * Z[o] + (1.0f / 9.0f) * P[o]
               + ((r == cc) ? (-1.0f / 6.0f) : 0.0f);
    }
    __syncthreads();
    {
        float acc[4][4] = {};
        if (act) mm64(P, acc == acc ? W : W, acc, i0, j0); // G1 = E^3 * W
        __syncthreads();
        // W = C1 + G1 = 1/3 I - 1/4 E + 1/5 E^2 + G1
        if (act) {
#pragma unroll
            for (int r = 0; r < 4; r++)
#pragma unroll
                for (int c2 = 0; c2 < 4; c2++) {
                    int o = (i0 + r) * ST + j0 + c2;
                    float v = acc[r][c2] - 0.25f * Y[o] + 0.2f * Z[o]
                              + ((i0 + r == j0 + c2) ? (1.0f / 3.0f) : 0.0f);
                    W[o] = v;
                    if (!diag) W[(j0 + c2) * ST + i0 + r] = v;
                }
        }
        __syncthreads();
    }
    {
        float acc[4][4] = {};
        if (act) mm64(P, W, acc, i0, j0);          // G2 = E^3 * W
        // log X = 8*(G2 + E - E^2/2) + 8*ln(gm)*I  (3 sqrt levels -> 2^3)
        if (act) {
            float* Lg = g_L + (size_t)m * DD;
            float lgd = 8.0f * logf(gm);
#pragma unroll
            for (int r = 0; r < 4; r++)
#pragma unroll
                for (int c2 = 0; c2 < 4; c2++) {
                    int o = (i0 + r) * ST + j0 + c2;
                    float v = 8.0f * (acc[r][c2] + Y[o] - 0.5f * Z[o])
                              + ((i0 + r == j0 + c2) ? lgd : 0.0f);
                    Lg[(i0 + r) * D + j0 + c2] = v;
                    if (!diag) Lg[(j0 + c2) * D + i0 + r] = v;
                }
        }
    }
}

// =====================================================================
// K2: pairwise squared distances + kernel weights  (direct, no cancellation)
// =====================================================================
__global__ void k_pds(const float* __restrict__ bwp)
{
    __shared__ float Li[32 * 65], Lj[32 * 65];
    const int tid = threadIdx.x;
    const int tx  = tid & 15, ty = tid >> 4;
    const int ib  = blockIdx.y * 32, jb = blockIdx.x * 32;
    const float eps = 1e-7f;
    float a00 = 0, a01 = 0, a10 = 0, a11 = 0;

    for (int kc = 0; kc < DD; kc += 64) {
        for (int idx = tid; idx < 2048; idx += 256) {
            int r = idx >> 6, kk = idx & 63;
            Li[r * 65 + kk] = g_L[(size_t)(ib + r) * DD + kc + kk];
            Lj[r * 65 + kk] = g_L[(size_t)(jb + r) * DD + kc + kk];
        }
        __syncthreads();
#pragma unroll 8
        for (int k = 0; k < 64; k++) {
            float li0 = Li[ty * 65 + k], li1 = Li[(ty + 16) * 65 + k];
            float lj0 = Lj[tx * 65 + k], lj1 = Lj[(tx + 16) * 65 + k];
            float d;
            d = lj0 - li0 + eps; a00 += d * d;
            d = lj1 - li0 + eps; a01 += d * d;
            d = lj0 - li1 + eps; a10 += d * d;
            d = lj1 - li1 + eps; a11 += d * d;
        }
        __syncthreads();
    }
    float bw = bwp[0];
    float g  = -0.5f / (bw * bw);
    g_W[(size_t)(ib + ty)      * NMAT + jb + tx]      = expf(g * a00);
    g_W[(size_t)(ib + ty)      * NMAT + jb + tx + 16] = expf(g * a01);
    g_W[(size_t)(ib + ty + 16) * NMAT + jb + tx]      = expf(g * a10);
    g_W[(size_t)(ib + ty + 16) * NMAT + jb + tx + 16] = expf(g * a11);
}

// =====================================================================
// K3: row sums and column sums of W
// =====================================================================
__global__ void k_sums()
{
    __shared__ float red[256];
    const int k = blockIdx.x, tid = threadIdx.x;

    red[tid] = g_W[(size_t)k * NMAT + tid];
    __syncthreads();
    for (int off = 128; off; off >>= 1) {
        if (tid < off) red[tid] += red[tid + off];
        __syncthreads();
    }
    if (tid == 0) g_rs[k] = red[0];
    __syncthreads();

    red[tid] = g_W[(size_t)tid * NMAT + k];
    __syncthreads();
    for (int off = 128; off; off >>= 1) {
        if (tid < off) red[tid] += red[tid + off];
        __syncthreads();
    }
    if (tid == 0) g_cs[k] = red[0];
}

// =====================================================================
// K4: B_k = logX_k*(1 - cs_k/rs_k) + (W^T L)_k / rs_k
// =====================================================================
__global__ void k_num()
{
    __shared__ float At[64 * ST];
    __shared__ float Bt[64 * ST];
    const int tid = threadIdx.x;
    const int i0  = (tid >> 4) * 4, j0 = (tid & 15) * 4;
    const int k0  = blockIdx.y * 64;
    const int c0  = blockIdx.x * 64;
    float acc[4][4] = {};

    for (int jc = 0; jc < NMAT; jc += 64) {
        for (int idx = tid; idx < 4096; idx += 256) {
            int jj = idx >> 6, kk = idx & 63;
            At[kk * ST + jj] = g_W[(size_t)(jc + jj) * NMAT + k0 + kk];
            Bt[jj * ST + kk] = g_L[(size_t)(jc + jj) * DD + c0 + kk];
        }
        __syncthreads();
        mm64(At, Bt, acc, i0, j0);
        __syncthreads();
    }
#pragma unroll
    for (int r = 0; r < 4; r++) {
        int k = k0 + i0 + r;
        float irs  = 1.0f / g_rs[k];
        float coef = 1.0f - g_cs[k] * irs;
#pragma unroll
        for (int c2 = 0; c2 < 4; c2++) {
            int col = c0 + j0 + c2;
            g_B[(size_t)k * DD + col] =
                acc[r][c2] * irs + coef * g_L[(size_t)k * DD + col];
        }
    }
}

// =====================================================================
// K5: matrix exp. Scaling (theta=0.5) + degree-9 Taylor via PS + squarings.
// Symmetric outputs -> triangle tiles + mirror.
// =====================================================================
__global__ void k_expm(float* __restrict__ out)
{
    extern __shared__ float sh[];
    float* A = sh;              // E
    float* Z = sh + D * ST;     // E^2 / squaring ping
    float* P = sh + 2 * D * ST; // E^3
    float* W = sh + 3 * D * ST; // scratch / squaring pong
    __shared__ float red[256];

    const int tid = threadIdx.x;
    const int m   = blockIdx.x;
    int i0, j0; bool act, diag;
    tri_map(tid, i0, j0, act, diag);
    const float* Bg = g_B + (size_t)m * DD;

    float p = 0.0f;
    for (int idx = tid; idx < DD; idx += 256) {
        float v = Bg[idx];
        A[(idx >> 6) * ST + (idx & 63)] = v;
        p += v * v;
    }
    red[tid] = p;
    __syncthreads();
    for (int off = 128; off; off >>= 1) {
        if (tid < off) red[tid] += red[tid + off];
        __syncthreads();
    }
    float nf = sqrtf(red[0]);
    int s = 0;
    while (nf > 0.5f && s < 30) { nf *= 0.5f; s++; }
    float sc = ldexpf(1.0f, -s);
    for (int idx = tid; idx < DD; idx += 256)
        A[(idx >> 6) * ST + (idx & 63)] *= sc;
    __syncthreads();

    // E^2, E^3
    {
        float acc[4][4] = {};
        if (act) mm64(A, A, acc, i0, j0);
        if (act) store_sym(Z, acc, i0, j0, diag);
        __syncthreads();
    }
    {
        float acc[4][4] = {};
        if (act) mm64(A, Z, acc, i0, j0);
        if (act) store_sym(P, acc, i0, j0, diag);
        __syncthreads();
    }
    // W = C2 + a9*E^3 = I/720 + E/5040 + E^2/40320 + E^3/362880
    for (int idx = tid; idx < DD; idx += 256) {
        int r = idx >> 6, cc = idx & 63;
        int o = r * ST + cc;
        W[o] = A[o] * (1.0f / 5040.0f) + Z[o] * (1.0f / 40320.0f)
               + P[o] * (1.0f / 362880.0f)
               + ((r == cc) ? (1.0f / 720.0f) : 0.0f);
    }
    __syncthreads();
    {
        float acc[4][4] = {};
        if (act) mm64(P, W, acc, i0, j0);          // G1
        __syncthreads();
        // W = C1 + G1 = I/6 + E/24 + E^2/120 + G1
        if (act) {
#pragma unroll
            for (int r = 0; r < 4; r++)
#pragma unroll
                for (int c2 = 0; c2 < 4; c2++) {
                    int o = (i0 + r) * ST + j0 + c2;
                    float v = acc[r][c2] + A[o] * (1.0f / 24.0f)
                              + Z[o] * (1.0f / 120.0f)
                              + ((i0 + r == j0 + c2) ? (1.0f / 6.0f) : 0.0f);
                    W[o] = v;
                    if (!diag) W[(j0 + c2) * ST + i0 + r] = v;
                }
        }
        __syncthreads();
    }
    {
        float acc[4][4] = {};
        if (act) mm64(P, W, acc, i0, j0);          // G2
        __syncthreads();
        // S = C0 + G2 = I + E + E^2/2 + G2  -> store into W
        if (act) {
#pragma unroll
            for (int r = 0; r < 4; r++)
#pragma unroll
                for (int c2 = 0; c2 < 4; c2++) {
                    int o = (i0 + r) * ST + j0 + c2;
                    float v = acc[r][c2] + A[o] + 0.5f * Z[o]
                              + ((i0 + r == j0 + c2) ? 1.0f : 0.0f);
                    W[o] = v;
                    if (!diag) W[(j0 + c2) * ST + i0 + r] = v;
                }
        }
        __syncthreads();
    }

    // square s times (ping-pong W <-> Z)
    float* cur = W;
    float* oth = Z;
    for (int q = 0; q < s; q++) {
        float acc[4][4] = {};
        if (act) mm64(cur, cur, acc, i0, j0);
        if (act) store_sym(oth, acc, i0, j0, diag); // distinct buffer: safe
        __syncthreads();
        float* t = cur; cur = oth; oth = t;
    }

    if (act) {
        float* Og = out + (size_t)m * DD;
#pragma unroll
        for (int r = 0; r < 4; r++)
#pragma unroll
            for (int c2 = 0; c2 < 4; c2++) {
                float v = cur[(i0 + r) * ST + j0 + c2];
                Og[(i0 + r) * D + j0 + c2] = v;
                if (!diag) Og[(j0 + c2) * D + i0 + r] = v;
            }
    }
}

// =====================================================================
extern "C" void kernel_launch(void* const* d_in, const int* in_sizes, int n_in,
                              void* d_out, int out_size)
{
    const float* X  = (const float*)d_in[0];
    const float* bw = (const float*)d_in[1];
    float* out      = (float*)d_out;

    const int shmem = 4 * D * ST * sizeof(float); // 69632 B
    cudaFuncSetAttribute(k_logm, cudaFuncAttributeMaxDynamicSharedMemorySize, shmem);
    cudaFuncSetAttribute(k_expm, cudaFuncAttributeMaxDynamicSharedMemorySize, shmem);

    k_logm<<<NMAT, 256, shmem>>>(X);
    k_pds<<<dim3(8, 8), 256>>>(bw);
    k_sums<<<NMAT, 256>>>();
    k_num<<<dim3(DD / 64, NMAT / 64), 256>>>();
    k_expm<<<NMAT, 256, shmem>>>(out);
}